// round 6
// baseline (speedup 1.0000x reference)
#include <cuda_runtime.h>

// SparseGrid volume renderer (svox2-style), GB300 sm_103a.
//
//  1) repack_kernel: pad [sh(27) | density(1)] into a 32-float (128 B,
//     line-aligned) voxel record: one corner record == one L1/L2 line.
//  2) render_kernel: ONE WARP PER RAY.
//     Prologue: exact in-bounds sample count via ballot (OOB is a suffix:
//     per-axis positions are monotone in t, box convex, origin interior),
//     using the reference's own per-sample predicate.
//     Main loop (counted, unroll 2): lane = corner*8 + float4-group; two
//     LDG.128 rounds cover corners x+0 / x+1 -> every LDG is 4 lines x
//     8 lanes (full-width wavefronts; 8 wf/sample = structural floor).
//     Reduction: corner butterfly (strides 8,16; 4 shfl) + fixed broadcast
//     assembly of (R,G,B,sigma) (10 shfl). Transmittance recurrence is
//     warp-uniform. Counted loop (no in-loop break) lets ptxas front-batch
//     both unrolled samples' LDGs -> MLP_p1=4.

#define RESO 128
#define NRAYS 16384
#define NSAMP 192
#define STEP 0.5f
#define NVOX (RESO * RESO * RESO)
#define REC 32                           // floats per record (one 128B line)

// 268 MB static scratch; device globals are zero-initialized, so the
// never-written pad floats (k=28..31) read as 0.0f.
__device__ __align__(128) float g_pack[(size_t)NVOX * REC];

// ---------------------------------------------------------------------------
// Repack: record v holds [sh[v*27 .. v*27+26], density[v], pad x4]
// ---------------------------------------------------------------------------
__global__ void repack_kernel(const float* __restrict__ density,
                              const float* __restrict__ sh) {
    const int NG = NVOX * 7;
    for (int i = blockIdx.x * blockDim.x + threadIdx.x; i < NG;
         i += gridDim.x * blockDim.x) {
        int v = i / 7;
        int g = i - v * 7;
        const float* s = sh + (size_t)v * 27 + g * 4;
        float4 o;
        if (g < 6) {
            o.x = __ldg(s + 0); o.y = __ldg(s + 1);
            o.z = __ldg(s + 2); o.w = __ldg(s + 3);
        } else {
            o.x = __ldg(s + 0); o.y = __ldg(s + 1);
            o.z = __ldg(s + 2); o.w = __ldg(density + v);
        }
        reinterpret_cast<float4*>(g_pack)[v * 8 + g] = o;
    }
}

// ---------------------------------------------------------------------------
// Render: warp per ray, cooperative per-sample gather.
// ---------------------------------------------------------------------------
__global__ __launch_bounds__(256)
void render_kernel(const float* __restrict__ origins,
                   const float* __restrict__ dirs,
                   float* __restrict__ out) {
    int gtid = blockIdx.x * blockDim.x + threadIdx.x;
    int ray  = gtid >> 5;           // grid is exactly NRAYS warps
    int lane = gtid & 31;

    float ox = __ldg(origins + ray * 3 + 0);
    float oy = __ldg(origins + ray * 3 + 1);
    float oz = __ldg(origins + ray * 3 + 2);
    float dx = __ldg(dirs + ray * 3 + 0);
    float dy = __ldg(dirs + ray * 3 + 1);
    float dz = __ldg(dirs + ray * 3 + 2);

    const unsigned FULL = 0xffffffffu;

    // ---- exact in-bounds sample count (reference predicate, ballot) ----
    // OOB is a suffix, so count = index of first failing sample.
    int cnt = NSAMP;
    #pragma unroll
    for (int c = 0; c < NSAMP / 32; c++) {
        float t  = ((float)(c * 32 + lane) + 0.5f) * STEP;
        float px = fmaf(t, dx, ox);
        float py = fmaf(t, dy, oy);
        float pz = fmaf(t, dz, oz);
        bool ib = px >= 0.f && px <= (float)(RESO - 1) &&
                  py >= 0.f && py <= (float)(RESO - 1) &&
                  pz >= 0.f && pz <= (float)(RESO - 1);
        unsigned bal = __ballot_sync(FULL, ib);
        if (bal != FULL) { cnt = c * 32 + __popc(bal); break; }
    }

    // Real SH basis (degree 2), svox2 convention.
    const float B0 = 0.28209479177387814f;
    const float B1 = -0.4886025119029199f * dy;
    const float B2 =  0.4886025119029199f * dz;
    const float B3 = -0.4886025119029199f * dx;
    const float B4 =  1.0925484305920792f * dx * dy;
    const float B5 = -1.0925484305920792f * dy * dz;
    const float B6 =  0.31539156525252005f * (2.f * dz * dz - dx * dx - dy * dy);
    const float B7 = -1.0925484305920792f * dx * dz;
    const float B8 =  0.5462742152960396f * (dx * dx - dy * dy);

    // ---- per-lane static role ------------------------------------------
    // j: float4 group of the record (0..7; 7 = padding, all-zero).
    // c0: corner for round 0 (x-bit 0); round 1 is corner c0+4 (x-bit 1).
    int j  = lane & 7;
    int c0 = lane >> 3;
    int cy = (c0 >> 1) & 1;
    int cz = c0 & 1;
    int lOff = (cy * RESO + cz) * 8 + j;      // float4 units
    const int X4 = RESO * RESO * 8;           // +x corner stride, float4 units

    // Per-lane basis constants for sh indices k = 4j..4j+3, split into two
    // channel accumulators A,B (channels: R,G,B, sigma=density basis 1).
    //   j0: A=R(b0..b3)   j1: A=R(b4..b7)   j2: A=R(b8)      B=G(b0,b1,b2)
    //   j3: A=G(b3..b6)   j4: A=G(b7,b8)    B=B(b0,b1)
    //   j5: A=B(b2..b5)   j6: A=B(b6,b7,b8) B=sigma(1)       j7: zero
    float cA0 = 0.f, cA1 = 0.f, cA2 = 0.f, cA3 = 0.f;
    float cB0 = 0.f, cB1 = 0.f, cB2 = 0.f, cB3 = 0.f;
    switch (j) {
        case 0: cA0 = B0; cA1 = B1; cA2 = B2; cA3 = B3; break;
        case 1: cA0 = B4; cA1 = B5; cA2 = B6; cA3 = B7; break;
        case 2: cA0 = B8; cB1 = B0; cB2 = B1; cB3 = B2; break;
        case 3: cA0 = B3; cA1 = B4; cA2 = B5; cA3 = B6; break;
        case 4: cA0 = B7; cA1 = B8; cB2 = B0; cB3 = B1; break;
        case 5: cA0 = B2; cA1 = B3; cA2 = B4; cA3 = B5; break;
        case 6: cA0 = B6; cA1 = B7; cA2 = B8; cB3 = 1.f; break;
        default: break;
    }

    const float4* gp = reinterpret_cast<const float4*>(g_pack);

    float T  = 1.f;
    float aR = 0.f, aG = 0.f, aB = 0.f;

    #pragma unroll 2
    for (int s = 0; s < cnt; s++) {
        float t  = ((float)s + 0.5f) * STEP;
        float px = fmaf(t, dx, ox);
        float py = fmaf(t, dy, oy);
        float pz = fmaf(t, dz, oz);

        float pfx = floorf(px), pfy = floorf(py), pfz = floorf(pz);
        // frac from UNclipped floor; upper-only index clip (lower implied
        // by the in-bounds predicate) — matches the reference quirk.
        float fx = px - pfx, fy = py - pfy, fz = pz - pfz;
        int ix = min((int)pfx, RESO - 2);
        int iy = min((int)pfy, RESO - 2);
        int iz = min((int)pfz, RESO - 2);

        int vb = ((ix * RESO + iy) * RESO + iz) * 8;   // float4 units

        // cooperative gather: 2 LDG.128, each 4 lines x 8 lanes (full wf)
        float4 v0 = __ldg(gp + (vb + lOff));
        float4 v1 = __ldg(gp + (vb + lOff + X4));

        // per-lane corner weights
        float wy  = cy ? fy : 1.f - fy;
        float wz  = cz ? fz : 1.f - fz;
        float wyz = wy * wz;
        float w0  = (1.f - fx) * wyz;   // corner x+0
        float w1  = fx * wyz;           // corner x+1

        float dA0 = fmaf(v0.w, cA3, fmaf(v0.z, cA2, fmaf(v0.y, cA1, v0.x * cA0)));
        float dB0 = fmaf(v0.w, cB3, fmaf(v0.z, cB2, fmaf(v0.y, cB1, v0.x * cB0)));
        float dA1 = fmaf(v1.w, cA3, fmaf(v1.z, cA2, fmaf(v1.y, cA1, v1.x * cA0)));
        float dB1 = fmaf(v1.w, cB3, fmaf(v1.z, cB2, fmaf(v1.y, cB1, v1.x * cB0)));

        float accA = fmaf(w1, dA1, w0 * dA0);
        float accB = fmaf(w1, dB1, w0 * dB0);

        // corner reduce: sum the 4 lane-subgroups (8 corners total);
        // afterwards every lane l holds totals for group j = l&7
        accA += __shfl_xor_sync(FULL, accA, 8);
        accA += __shfl_xor_sync(FULL, accA, 16);
        accB += __shfl_xor_sync(FULL, accB, 8);
        accB += __shfl_xor_sync(FULL, accB, 16);

        // fixed broadcast assembly of the 4 per-sample channel totals
        float chR = __shfl_sync(FULL, accA, 0)
                  + __shfl_sync(FULL, accA, 1)
                  + __shfl_sync(FULL, accA, 2);
        float chG = __shfl_sync(FULL, accB, 2)
                  + __shfl_sync(FULL, accA, 3)
                  + __shfl_sync(FULL, accA, 4);
        float chB = __shfl_sync(FULL, accB, 4)
                  + __shfl_sync(FULL, accA, 5)
                  + __shfl_sync(FULL, accA, 6);
        float chS = __shfl_sync(FULL, accB, 6);

        // warp-uniform transmittance recurrence
        float sigma = (chS > 1e-10f) ? chS : 0.f;   // implies max(sigma,0)
        float e = __expf(-sigma * STEP);
        float w = T * (1.f - e);
        T *= e;

        aR = fmaf(w, fmaxf(chR + 0.5f, 0.f), aR);
        aG = fmaf(w, fmaxf(chG + 0.5f, 0.f), aG);
        aB = fmaf(w, fmaxf(chB + 0.5f, 0.f), aB);
    }

    if (lane == 0) {
        // EMPTY_BRIGHT = 1.0; OOB samples contribute log_att = 0
        out[ray * 3 + 0] = aR + T;
        out[ray * 3 + 1] = aG + T;
        out[ray * 3 + 2] = aB + T;
    }
}

extern "C" void kernel_launch(void* const* d_in, const int* in_sizes, int n_in,
                              void* d_out, int out_size) {
    const float* origins = (const float*)d_in[0];
    const float* dirs    = (const float*)d_in[1];
    const float* density = (const float*)d_in[2];
    const float* sh      = (const float*)d_in[3];
    float* out = (float*)d_out;

    const int NG = NVOX * 7;
    repack_kernel<<<(NG + 255) / 256, 256>>>(density, sh);
    render_kernel<<<(NRAYS * 32) / 256, 256>>>(origins, dirs, out);
}

// round 8
// speedup vs baseline: 1.2618x; 1.2618x over previous
#include <cuda_runtime.h>
#include <cuda_fp16.h>

// SparseGrid volume renderer (svox2-style), GB300 sm_103a.
//
//  1) repack_kernel: [sh(27) fp16 | pad | density fp32 | pad] -> 64B record
//     (4 float4 groups). One record = half an L1 line; sh precision fp16
//     (rel 4.9e-4, budget ok), density/weights/transmittance stay fp32.
//  2) render_kernel: persistent warps, atomic ray ticket (reset_kernel zeroes
//     the counter each launch). ONE WARP PER RAY:
//     - prologue ballot gives the exact in-bounds sample count (OOB is a
//       suffix: positions monotone in t, box convex, origin interior).
//     - per sample: lane = corner*4 + group; ONE LDG.128 gathers all 8
//       corner records (4 float4-groups each).
//     - reduction: corner butterfly (strides 4,8,16; 6 shfl) + 2 cross-group
//       shfl + 1 sigma broadcast = 9 shfl. Channel ownership: lane0=R,
//       lane1=G, lane2=B, lane3=sigma.
//     - transmittance recurrence warp-uniform; per-lane single accumulator.

#define RESO   128
#define NRAYS  16384
#define NSAMP  192
#define STEP   0.5f
#define NVOX   (RESO * RESO * RESO)

// 128^3 * 64B = 134 MB packed grid (every group written by repack)
__device__ __align__(128) float4 g_pack[(size_t)NVOX * 4];
__device__ unsigned g_ticket;

__global__ void reset_kernel() { g_ticket = 0u; }

__device__ __forceinline__ float pack2f(float lo, float hi) {
    __half2 h = __floats2half2_rn(lo, hi);
    return __uint_as_float(*reinterpret_cast<unsigned*>(&h));
}

// ---------------------------------------------------------------------------
// Repack: record v = g0[sh0..7] g1[sh8..15] g2[sh16..23]
//                    g3[sh24,25 | sh26,0 | density(f32) | 0.f]
// ---------------------------------------------------------------------------
__global__ void repack_kernel(const float* __restrict__ density,
                              const float* __restrict__ sh) {
    const int NG = NVOX * 4;
    for (int i = blockIdx.x * blockDim.x + threadIdx.x; i < NG;
         i += gridDim.x * blockDim.x) {
        int v = i >> 2, g = i & 3;
        const float* s = sh + (size_t)v * 27 + g * 8;
        float4 o;
        if (g < 3) {
            o.x = pack2f(__ldg(s + 0), __ldg(s + 1));
            o.y = pack2f(__ldg(s + 2), __ldg(s + 3));
            o.z = pack2f(__ldg(s + 4), __ldg(s + 5));
            o.w = pack2f(__ldg(s + 6), __ldg(s + 7));
        } else {
            o.x = pack2f(__ldg(s + 0), __ldg(s + 1));   // sh24, sh25
            o.y = pack2f(__ldg(s + 2), 0.f);            // sh26, pad
            o.z = __ldg(density + v);                   // fp32 density
            o.w = 0.f;                                  // pad (halves 0,0)
        }
        g_pack[i] = o;
    }
}

// ---------------------------------------------------------------------------
// Render: persistent warps, one warp per ray.
// ---------------------------------------------------------------------------
__global__ __launch_bounds__(128)
void render_kernel(const float* __restrict__ origins,
                   const float* __restrict__ dirs,
                   float* __restrict__ out) {
    const unsigned FULL = 0xffffffffu;
    int lane = threadIdx.x & 31;

    // lane role: j = float4 group (0..3), corner bits (cx,cy,cz)
    int j  = lane & 3;
    int cz = (lane >> 2) & 1;
    int cy = (lane >> 3) & 1;
    int cx = (lane >> 4) & 1;
    int lOff = (cx * RESO * RESO + cy * RESO + cz) * 4 + j;  // float4 units
    const bool j0p = (j == 0), j1p = (j == 1), j3p = (j == 3);
    const float4* gp = g_pack;

    for (;;) {
        unsigned r = 0;
        if (lane == 0) r = atomicAdd(&g_ticket, 1u);
        r = __shfl_sync(FULL, r, 0);
        if (r >= NRAYS) break;

        float ox = __ldg(origins + r * 3 + 0);
        float oy = __ldg(origins + r * 3 + 1);
        float oz = __ldg(origins + r * 3 + 2);
        float dx = __ldg(dirs + r * 3 + 0);
        float dy = __ldg(dirs + r * 3 + 1);
        float dz = __ldg(dirs + r * 3 + 2);

        // exact in-bounds sample count (reference predicate; OOB is a suffix)
        int cnt = NSAMP;
        #pragma unroll
        for (int c = 0; c < NSAMP / 32; c++) {
            float tt = ((float)(c * 32 + lane) + 0.5f) * STEP;
            float qx = fmaf(tt, dx, ox);
            float qy = fmaf(tt, dy, oy);
            float qz = fmaf(tt, dz, oz);
            bool ib = qx >= 0.f && qx <= (float)(RESO - 1) &&
                      qy >= 0.f && qy <= (float)(RESO - 1) &&
                      qz >= 0.f && qz <= (float)(RESO - 1);
            unsigned bal = __ballot_sync(FULL, ib);
            if (bal != FULL) { cnt = c * 32 + __popc(bal); break; }
        }

        // SH basis (degree 2), svox2 convention
        const float B0 = 0.28209479177387814f;
        const float B1 = -0.4886025119029199f * dy;
        const float B2 =  0.4886025119029199f * dz;
        const float B3 = -0.4886025119029199f * dx;
        const float B4 =  1.0925484305920792f * dx * dy;
        const float B5 = -1.0925484305920792f * dy * dz;
        const float B6 =  0.31539156525252005f * (2.f * dz * dz - dx * dx - dy * dy);
        const float B7 = -1.0925484305920792f * dx * dz;
        const float B8 =  0.5462742152960396f * (dx * dx - dy * dy);

        // per-lane coefficients for halves k = 8j..8j+7
        //  A/B channel split:  j0: A=R(b0..b7)          j1: A=R(b8), B=G(b0..b6)
        //                      j2: A=G(b7,b8), B=Bl(b0..b5)
        //                      j3: A=Bl(b6,b7,b8), B=sigma (density, direct)
        float cA0=0.f,cA1=0.f,cA2=0.f,cA3=0.f,cA4=0.f,cA5=0.f,cA6=0.f,cA7=0.f;
        float cB0=0.f,cB1=0.f,cB2=0.f,cB3=0.f,cB4=0.f,cB5=0.f,cB6=0.f,cB7=0.f;
        switch (j) {
            case 0: cA0=B0;cA1=B1;cA2=B2;cA3=B3;cA4=B4;cA5=B5;cA6=B6;cA7=B7; break;
            case 1: cA0=B8; cB1=B0;cB2=B1;cB3=B2;cB4=B3;cB5=B4;cB6=B5;cB7=B6; break;
            case 2: cA0=B7;cA1=B8; cB2=B0;cB3=B1;cB4=B2;cB5=B3;cB6=B4;cB7=B5; break;
            default: cA0=B6;cA1=B7;cA2=B8; break;
        }

        float T = 1.f, acc = 0.f;
        float t = 0.25f;                 // (0+0.5)*STEP; increments exact in fp32
        #pragma unroll 2
        for (int s = 0; s < cnt; s++, t += STEP) {
            float px = fmaf(t, dx, ox);
            float py = fmaf(t, dy, oy);
            float pz = fmaf(t, dz, oz);

            float pfx = floorf(px), pfy = floorf(py), pfz = floorf(pz);
            // frac from UNclipped floor; upper-only index clip (lower implied
            // by the in-bounds predicate) — matches the reference quirk.
            float fx = px - pfx, fy = py - pfy, fz = pz - pfz;
            int ix = min((int)pfx, RESO - 2);
            int iy = min((int)pfy, RESO - 2);
            int iz = min((int)pfz, RESO - 2);

            int vb = ((ix * RESO + iy) * RESO + iz) * 4;   // float4 units
            float4 v = __ldg(gp + (vb + lOff));            // 1 LDG.128/sample

            float2 f01 = __half22float2(*reinterpret_cast<const __half2*>(&v.x));
            float2 f23 = __half22float2(*reinterpret_cast<const __half2*>(&v.y));
            unsigned zb = j3p ? 0u : __float_as_uint(v.z); // j3's v.z is fp32 density
            float2 f45 = __half22float2(*reinterpret_cast<const __half2*>(&zb));
            float2 f67 = __half22float2(*reinterpret_cast<const __half2*>(&v.w));

            float dA = fmaf(f67.y, cA7, fmaf(f67.x, cA6, fmaf(f45.y, cA5,
                       fmaf(f45.x, cA4, fmaf(f23.y, cA3, fmaf(f23.x, cA2,
                       fmaf(f01.y, cA1, f01.x * cA0)))))));
            float dB = fmaf(f67.y, cB7, fmaf(f67.x, cB6, fmaf(f45.y, cB5,
                       fmaf(f45.x, cB4, fmaf(f23.y, cB3, fmaf(f23.x, cB2,
                       fmaf(f01.y, cB1, f01.x * cB0)))))));
            dB = j3p ? v.z : dB;                           // sigma = density

            // per-lane trilinear corner weight
            float wx = cx ? fx : 1.f - fx;
            float wy = cy ? fy : 1.f - fy;
            float wz = cz ? fz : 1.f - fz;
            float w  = wx * wy * wz;
            float A  = w * dA;
            float Bv = w * dB;

            // corner butterfly (8 corners live at lane strides 4,8,16)
            A  += __shfl_xor_sync(FULL, A, 4);
            A  += __shfl_xor_sync(FULL, A, 8);
            A  += __shfl_xor_sync(FULL, A, 16);
            Bv += __shfl_xor_sync(FULL, Bv, 4);
            Bv += __shfl_xor_sync(FULL, Bv, 8);
            Bv += __shfl_xor_sync(FULL, Bv, 16);

            // cross-group assembly: R@j0 = A0+A1, G@j1 = B1+A2,
            // Bl@j2 = B2+A3, S@j3 = B3
            float tA1 = __shfl_xor_sync(FULL, A, 1);
            float tA3 = __shfl_xor_sync(FULL, A, 3);
            float add = j1p ? tA3 : tA1;
            add = j3p ? 0.f : add;
            float ch = (j0p ? A : Bv) + add;

            float sigma = __shfl_sync(FULL, ch, 3);        // lane3 holds S

            // warp-uniform transmittance recurrence
            sigma = (sigma > 1e-10f) ? sigma : 0.f;        // implies max(.,0)
            float e  = __expf(-sigma * STEP);
            float ws = T * (1.f - e);
            T *= e;

            // lane-owned channel accumulate (lane3 accumulates junk, unread)
            acc = fmaf(ws, fmaxf(ch + 0.5f, 0.f), acc);
        }

        if (lane < 3) out[r * 3 + lane] = acc + T;         // EMPTY_BRIGHT = 1
    }
}

extern "C" void kernel_launch(void* const* d_in, const int* in_sizes, int n_in,
                              void* d_out, int out_size) {
    const float* origins = (const float*)d_in[0];
    const float* dirs    = (const float*)d_in[1];
    const float* density = (const float*)d_in[2];
    const float* sh      = (const float*)d_in[3];
    float* out = (float*)d_out;

    reset_kernel<<<1, 1>>>();
    const int NG = NVOX * 4;
    repack_kernel<<<(NG + 255) / 256, 256>>>(density, sh);
    render_kernel<<<1480, 128>>>(origins, dirs, out);
}